// round 17
// baseline (speedup 1.0000x reference)
#include <cuda_runtime.h>
#include <cuda_fp16.h>
#include <cstdint>

// ============================================================================
// LoRALinear: out = x @ W^T + b + 2 * x @ (A @ B^T)^T
//   x:(2,4096,4096) f32, W:(4096,4096), b:(4096), A:(4096,8), B:(4096,8)
//
// fp16 m16n8k16 path. CTA 128x256, BK=64 halves, 4-stage cp.async,
// 8 warps x 64x64, fp32 accumulators, 1 CTA/SM, ldmatrix.x4 fragments,
// fragment double-buffering.
// prep_w: smem-staged B (R12-proven), 8 rows/block x 512 blocks for 2x CTA
// parallelism on the DRAM-bound W stream.
// R15: container infra flake (never reached compile); resubmitting.
// ============================================================================

#define BM 128
#define BN 256
#define BKH 64                 // k-tile in halves (128 bytes per row)
#define STAGES 4
#define KDIM 4096
#define NDIM 4096
#define MDIM 8192
#define KTILES (KDIM / BKH)    // 64

// per-stage b32 words: A = 128 rows x 32, B = 256 rows x 32
#define A_TILE_W (BM * 32)                   // 4096
#define B_TILE_W (BN * 32)                   // 8192
#define STAGE_W  (A_TILE_W + B_TILE_W)       // 12288 (48KB)
#define SMEM_BYTES (STAGES * STAGE_W * 4)    // 196608

// Scratch (device-global; runtime allocation prohibited)
__device__ __half g_Wh[(size_t)NDIM * KDIM];   // 32 MB
__device__ __half g_xh[(size_t)MDIM * KDIM];   // 64 MB

// ---------------------------------------------------------------------------
// helpers
// ---------------------------------------------------------------------------
__device__ __forceinline__ uint32_t smem_u32(const void* p) {
    uint32_t a;
    asm("{ .reg .u64 t; cvta.to.shared.u64 t, %1; cvt.u32.u64 %0, t; }"
        : "=r"(a) : "l"(p));
    return a;
}

__device__ __forceinline__ void cp_async16(uint32_t dst, const void* src) {
    asm volatile("cp.async.cg.shared.global [%0], [%1], 16;"
                 :: "r"(dst), "l"(src) : "memory");
}
#define CP_COMMIT() asm volatile("cp.async.commit_group;" ::: "memory")
#define CP_WAIT(n)  asm volatile("cp.async.wait_group %0;" :: "n"(n) : "memory")

__device__ __forceinline__ uint32_t h2_bits(__half2 h) {
    union { __half2 h; uint32_t u; } cvt;
    cvt.h = h;
    return cvt.u;
}

// m16n8k16 f16 MMA, fp32 accum, D += A*B
__device__ __forceinline__ void mma_f16(float* d, const uint32_t* a,
                                        const uint32_t* b) {
    asm volatile(
        "mma.sync.aligned.m16n8k16.row.col.f32.f16.f16.f32 "
        "{%0,%1,%2,%3}, {%4,%5,%6,%7}, {%8,%9}, {%0,%1,%2,%3};"
        : "+f"(d[0]), "+f"(d[1]), "+f"(d[2]), "+f"(d[3])
        : "r"(a[0]), "r"(a[1]), "r"(a[2]), "r"(a[3]), "r"(b[0]), "r"(b[1]));
}

// ldmatrix x4: lane l supplies the row address of matrix (l>>3)
__device__ __forceinline__ void ldsm_x4(uint32_t* r, uint32_t addr) {
    asm volatile(
        "ldmatrix.sync.aligned.m8n8.x4.shared.b16 {%0,%1,%2,%3}, [%4];"
        : "=r"(r[0]), "=r"(r[1]), "=r"(r[2]), "=r"(r[3]) : "r"(addr));
}

// swizzled b32 index within a (rows x 32 b32) tile: XOR 16B-chunk by row&7
__device__ __forceinline__ int swz_idx(int row, int col) {
    return row * 32 + ((((col >> 2) ^ row) & 7) << 2) + (col & 3);
}

// ---------------------------------------------------------------------------
// Kernel 1: W' = fp16_rn(W + 2 * A @ B^T)   (W:(N,K) row-major)
// smem-staged B (proven R12 structure), 8 rows/block x 512 blocks.
// ---------------------------------------------------------------------------
__global__ void prep_w_kernel(const float* __restrict__ W,
                              const float* __restrict__ A,
                              const float* __restrict__ Bm) {
    __shared__ float sA[8 * 8];
    __shared__ float sB[1024 * 9];   // 1024 input rows x 8 ranks, pad stride 9

    const int t = threadIdx.x;
    const int bo = blockIdx.x;       // 8 rows per block

    if (t < 64) sA[t] = A[(bo * 8 + (t >> 3)) * 8 + (t & 7)];

    for (int c = 0; c < 4; c++) {
        const int i0 = c * 1024;
        __syncthreads();
        // stage B rows [i0, i0+1024)  (8192 floats, coalesced)
        for (int j = 0; j < 32; j++) {
            int li = t + j * 256;
            sB[(li >> 3) * 9 + (li & 7)] = Bm[i0 * 8 + li];
        }
        __syncthreads();
        for (int ol = 0; ol < 8; ol++) {
            const int o = bo * 8 + ol;
            float a0 = sA[ol * 8 + 0], a1 = sA[ol * 8 + 1];
            float a2 = sA[ol * 8 + 2], a3 = sA[ol * 8 + 3];
            float a4 = sA[ol * 8 + 4], a5 = sA[ol * 8 + 5];
            float a6 = sA[ol * 8 + 6], a7 = sA[ol * 8 + 7];
            for (int j = 0; j < 4; j++) {
                int il = t + j * 256;
                const float* br = &sB[il * 9];
                float d = a0 * br[0] + a1 * br[1] + a2 * br[2] + a3 * br[3]
                        + a4 * br[4] + a5 * br[5] + a6 * br[6] + a7 * br[7];
                int idx = o * KDIM + i0 + il;
                g_Wh[idx] = __float2half_rn(W[idx] + 2.0f * d);
            }
        }
    }
}

// ---------------------------------------------------------------------------
// Kernel 2: xh = fp16_rn(x)
// ---------------------------------------------------------------------------
__global__ void conv_x_kernel(const float4* __restrict__ x, int n8) {
    uint4* xh = reinterpret_cast<uint4*>(g_xh);
    for (int i = blockIdx.x * blockDim.x + threadIdx.x; i < n8;
         i += gridDim.x * blockDim.x) {
        float4 f0 = x[2 * i];
        float4 f1 = x[2 * i + 1];
        uint4 v;
        v.x = h2_bits(__floats2half2_rn(f0.x, f0.y));
        v.y = h2_bits(__floats2half2_rn(f0.z, f0.w));
        v.z = h2_bits(__floats2half2_rn(f1.x, f1.y));
        v.w = h2_bits(__floats2half2_rn(f1.z, f1.w));
        xh[i] = v;
    }
}

// ---------------------------------------------------------------------------
// Kernel 3: out = xh @ Wh^T + bias  (mma.sync f16 k16 + ldmatrix, 128x256)
// ---------------------------------------------------------------------------
__global__ __launch_bounds__(256, 1)
void lora_gemm_f16(const float* __restrict__ bias, float* __restrict__ out) {
    extern __shared__ float smem[];
    __shared__ float sbias[BN];

    const uint32_t sbase = smem_u32(smem);
    const int tid = threadIdx.x;
    const int wid = tid >> 5;
    const int lane = tid & 31;
    const int ntile = blockIdx.x;   // 0..15 (fastest: W' L2-resident)
    const int mtile = blockIdx.y;   // 0..63

    // warp tile 64x64: warp_m {0,1}, warp_n {0..3}
    const int mrow_s = (wid & 1) * 64;
    const int ncol_s = (wid >> 1) * 64;
    const int r0 = lane >> 2;       // epilogue row
    const int c0 = lane & 3;        // epilogue col pair

    sbias[tid] = bias[ntile * BN + tid];

    // ---- producer offsets ----
    const int prow = tid >> 3;           // 0..31
    const int pch  = tid & 7;            // 0..7
    const __half* Abase = g_xh + (size_t)(mtile * BM + prow) * KDIM + pch * 8;
    const __half* Bbase = g_Wh + (size_t)(ntile * BN + prow) * KDIM + pch * 8;
    uint32_t aswz[4], bswz[8];
    #pragma unroll
    for (int i = 0; i < 4; i++) aswz[i] = (uint32_t)swz_idx(prow + i * 32, pch * 4) * 4u;
    #pragma unroll
    for (int i = 0; i < 8; i++) bswz[i] = (uint32_t)swz_idx(prow + i * 32, pch * 4) * 4u;

    auto load_tile = [&](int kt, int s) {
        const uint32_t abytes = sbase + (uint32_t)(s * STAGE_W) * 4u;
        const uint32_t bbytes = abytes + A_TILE_W * 4u;
        const int kbase = kt * BKH;   // halves
        #pragma unroll
        for (int i = 0; i < 4; i++)            // A: 128 rows
            cp_async16(abytes + aswz[i], Abase + (size_t)(i * 32) * KDIM + kbase);
        #pragma unroll
        for (int i = 0; i < 8; i++)            // B: 256 rows
            cp_async16(bbytes + bswz[i], Bbase + (size_t)(i * 32) * KDIM + kbase);
        CP_COMMIT();
    };

    // ---- ldmatrix per-lane addressing (validated R12) ----
    const int alr = lane & 7;
    const int a_c4 = (lane >> 4) & 1;              // A chunk offset 0/1
    const int b_c4 = (lane >> 3) & 1;              // B chunk offset 0/1
    uint32_t abase[4], bbase4[4];
    int arow7[4], brow7[4];
    #pragma unroll
    for (int mt = 0; mt < 4; mt++) {
        int row = mrow_s + mt * 16 + ((lane >> 3) & 1) * 8 + alr;
        abase[mt] = (uint32_t)row * 128u;
        arow7[mt] = row & 7;
    }
    #pragma unroll
    for (int np = 0; np < 4; np++) {
        int row = ncol_s + np * 16 + ((lane >> 4) & 1) * 8 + alr;
        bbase4[np] = (uint32_t)(A_TILE_W * 4) + (uint32_t)row * 128u;
        brow7[np] = row & 7;
    }

    #pragma unroll
    for (int s = 0; s < STAGES - 1; s++) load_tile(s, s);

    float acc[4][8][4];
    #pragma unroll
    for (int mt = 0; mt < 4; mt++)
        #pragma unroll
        for (int nt = 0; nt < 8; nt++)
            #pragma unroll
            for (int q = 0; q < 4; q++) acc[mt][nt][q] = 0.0f;

    for (int kt = 0; kt < KTILES; kt++) {
        const int s = kt & (STAGES - 1);
        if (kt <= KTILES - 3)       CP_WAIT(2);
        else if (kt == KTILES - 2)  CP_WAIT(1);
        else                        CP_WAIT(0);
        __syncthreads();

        const int nk = kt + STAGES - 1;
        if (nk < KTILES) load_tile(nk, nk & (STAGES - 1));

        const uint32_t stage_b = sbase + (uint32_t)(s * STAGE_W) * 4u;

        // frag double-buffer across the ks loop
        uint32_t a[2][4][4], bfr[2][4][4];
        auto load_frags = [&](int ks, int buf) {
            const int ch = 2 * ks;
            #pragma unroll
            for (int mt = 0; mt < 4; mt++)
                ldsm_x4(a[buf][mt], stage_b + abase[mt]
                        + (uint32_t)((((ch + a_c4) ^ arow7[mt]) & 7) << 4));
            #pragma unroll
            for (int np = 0; np < 4; np++)
                ldsm_x4(bfr[buf][np], stage_b + bbase4[np]
                        + (uint32_t)((((ch + b_c4) ^ brow7[np]) & 7) << 4));
        };

        load_frags(0, 0);
        #pragma unroll
        for (int ks = 0; ks < 4; ks++) {
            const int cur = ks & 1;
            if (ks < 3) load_frags(ks + 1, cur ^ 1);
            #pragma unroll
            for (int mt = 0; mt < 4; mt++)
                #pragma unroll
                for (int nt = 0; nt < 8; nt++)
                    mma_f16(acc[mt][nt], a[cur][mt],
                            &bfr[cur][nt >> 1][(nt & 1) * 2]);
        }
    }

    // ---- epilogue: float2 stores with bias ----
    #pragma unroll
    for (int mt = 0; mt < 4; mt++) {
        const int m = mtile * BM + mrow_s + mt * 16 + r0;
        #pragma unroll
        for (int nt = 0; nt < 8; nt++) {
            const int nloc = ncol_s + nt * 8 + 2 * c0;
            const int n = ntile * BN + nloc;
            const float b0 = sbias[nloc], b1 = sbias[nloc + 1];
            float2 v0 = make_float2(acc[mt][nt][0] + b0, acc[mt][nt][1] + b1);
            float2 v1 = make_float2(acc[mt][nt][2] + b0, acc[mt][nt][3] + b1);
            *reinterpret_cast<float2*>(out + (size_t)m * NDIM + n) = v0;
            *reinterpret_cast<float2*>(out + (size_t)(m + 8) * NDIM + n) = v1;
        }
    }
}

// ---------------------------------------------------------------------------
extern "C" void kernel_launch(void* const* d_in, const int* in_sizes, int n_in,
                              void* d_out, int out_size) {
    const float* x = (const float*)d_in[0];   // (2,4096,4096)
    const float* W = (const float*)d_in[1];   // (4096,4096)
    const float* b = (const float*)d_in[2];   // (4096)
    const float* A = (const float*)d_in[3];   // (4096,8)
    const float* B = (const float*)d_in[4];   // (4096,8)
    float* out = (float*)d_out;

    cudaFuncSetAttribute(lora_gemm_f16,
                         cudaFuncAttributeMaxDynamicSharedMemorySize, SMEM_BYTES);

    prep_w_kernel<<<512, 256>>>(W, A, B);
    conv_x_kernel<<<2048, 256>>>(reinterpret_cast<const float4*>(x),
                                 (int)((size_t)MDIM * KDIM / 8));
    lora_gemm_f16<<<dim3(NDIM / BN, MDIM / BM), 256, SMEM_BYTES>>>(b, out);
}